// round 7
// baseline (speedup 1.0000x reference)
#include <cuda_runtime.h>
#include <math.h>

#define NE 3
#define BB 8
#define TT 1024
#define HH 128
#define EE 64
#define LL 3
#define DI 256
#define SN 16
#define KC 4
#define RR 8
#define MM (BB*TT)         // 8192 rows per encoder
#define EPSF 1e-7f

typedef unsigned long long ull;

// ---------------- scratch (no allocations allowed) ----------------
__device__ float g_h0[NE*MM*HH];
__device__ float g_h1[NE*MM*HH];
__device__ float g_xz[NE*MM*2*DI];
__device__ float g_xc[NE*MM*DI];
__device__ float g_xdbl[NE*MM*40];
__device__ float g_dt[NE*MM*DI];
__device__ float g_y[NE*MM*DI];

__device__ __forceinline__ float siluf(float v) { return v / (1.f + __expf(-v)); }

// packed fp32 FMA: c = a*b + c on both 32-bit halves (FFMA2)
#define FMA2(c, a, b) asm("fma.rn.f32x2 %0, %1, %2, %0;" : "+l"(c) : "l"(a), "l"(b))

__device__ __forceinline__ float lo32(ull x) { return __uint_as_float((unsigned)(x & 0xffffffffULL)); }
__device__ __forceinline__ float hi32(ull x) { return __uint_as_float((unsigned)(x >> 32)); }

// ---------------- embed: h = x * w + b ----------------
__global__ void k_embed(const float* __restrict__ x, const float* __restrict__ w,
                        const float* __restrict__ b) {
    int idx = blockIdx.x * blockDim.x + threadIdx.x;
    if (idx >= NE*MM*HH) return;
    int hh  = idx % HH;
    int row = (idx / HH) % MM;
    int ne  = idx / (HH*MM);
    g_h0[idx] = x[ne*MM + row] * w[ne*HH + hh] + b[ne*HH + hh];
}

// ======== universal SGEMM, FFMA2 inner loop ========
// 64x64 tile, BK=16, 4x4 microtile (as 4x2 f32x2), double-buffered.
// C[m][n] = sum_k A[m][k] * W[n][k]
// epi==0: plain   epi==1: C = tanh(C + bias[n])
// epi==2: also dt = softplus(C[:, 0:8] @ dw^T + db) into dtout
__global__ void __launch_bounds__(256) sgemm64(
    const float* __restrict__ A, const float* __restrict__ W,
    const float* __restrict__ bias, float* __restrict__ C,
    int Nn, int Kk, int sA, int sW, int sC, int sBias, int epi, int Nvalid,
    const float* __restrict__ dw, const float* __restrict__ db,
    float* __restrict__ dtout)
{
    __shared__ float2 As2[2][16][68];   // A duplicated: (a, a) at [k][m]
    __shared__ float  Bs[2][16][68];    // [k][n]
    __shared__ float  xs[64][9];

    int ne = blockIdx.z;
    A += ne * sA; W += ne * sW; C += ne * sC;
    int m0 = blockIdx.x * 64, n0 = blockIdx.y * 64;
    int tid = threadIdx.x;
    int tx = tid & 15, ty = tid >> 4;
    int lr = tid >> 2;             // 0..63 (tile row)
    int kq = (tid & 3) * 4;        // k sub-offset 0,4,8,12

    const float* ap = A + (m0 + lr) * Kk + kq;
    bool wok = (n0 + lr) < Nvalid;
    const float* wp = W + (wok ? (n0 + lr) : 0) * Kk + kq;

    ull acc[4][2];
#pragma unroll
    for (int i = 0; i < 4; i++) { acc[i][0] = 0ULL; acc[i][1] = 0ULL; }

    float4 av, wv;
    const float4 fz = make_float4(0.f, 0.f, 0.f, 0.f);

#define STAGE_STORE(buf)                                                     \
    { As2[buf][kq+0][lr] = make_float2(av.x, av.x);                          \
      As2[buf][kq+1][lr] = make_float2(av.y, av.y);                          \
      As2[buf][kq+2][lr] = make_float2(av.z, av.z);                          \
      As2[buf][kq+3][lr] = make_float2(av.w, av.w);                          \
      Bs[buf][kq+0][lr] = wv.x; Bs[buf][kq+1][lr] = wv.y;                    \
      Bs[buf][kq+2][lr] = wv.z; Bs[buf][kq+3][lr] = wv.w; }

#define STAGE_COMPUTE(buf)                                                   \
    _Pragma("unroll")                                                        \
    for (int k = 0; k < 16; k++) {                                           \
        ulonglong2 a01 = *(const ulonglong2*)&As2[buf][k][ty*4];             \
        ulonglong2 a23 = *(const ulonglong2*)&As2[buf][k][ty*4+2];           \
        ulonglong2 bp  = *(const ulonglong2*)&Bs[buf][k][tx*4];              \
        FMA2(acc[0][0], a01.x, bp.x); FMA2(acc[0][1], a01.x, bp.y);          \
        FMA2(acc[1][0], a01.y, bp.x); FMA2(acc[1][1], a01.y, bp.y);          \
        FMA2(acc[2][0], a23.x, bp.x); FMA2(acc[2][1], a23.x, bp.y);          \
        FMA2(acc[3][0], a23.y, bp.x); FMA2(acc[3][1], a23.y, bp.y);          \
    }

    // preload k=0 into buffer 0
    av = *(const float4*)ap;
    wv = wok ? *(const float4*)wp : fz;
    STAGE_STORE(0);
    __syncthreads();

    for (int k0 = 0; k0 < Kk; k0 += 32) {
        bool l1 = (k0 + 16) < Kk;
        if (l1) {
            av = *(const float4*)(ap + k0 + 16);
            wv = wok ? *(const float4*)(wp + k0 + 16) : fz;
        }
        STAGE_COMPUTE(0);
        if (l1) { STAGE_STORE(1); __syncthreads(); }
        bool l2 = (k0 + 32) < Kk;
        if (l2) {
            av = *(const float4*)(ap + k0 + 32);
            wv = wok ? *(const float4*)(wp + k0 + 32) : fz;
        }
        if (l1) STAGE_COMPUTE(1);
        if (l2) { STAGE_STORE(0); __syncthreads(); }
    }

    // epilogue
    if (n0 + tx*4 < Nvalid) {
#pragma unroll
        for (int i = 0; i < 4; i++) {
            int m = m0 + ty*4 + i;
            float4 v = make_float4(lo32(acc[i][0]), hi32(acc[i][0]),
                                   lo32(acc[i][1]), hi32(acc[i][1]));
            if (epi == 1) {
                v.x = tanhf(v.x + bias[ne*sBias + n0 + tx*4 + 0]);
                v.y = tanhf(v.y + bias[ne*sBias + n0 + tx*4 + 1]);
                v.z = tanhf(v.z + bias[ne*sBias + n0 + tx*4 + 2]);
                v.w = tanhf(v.w + bias[ne*sBias + n0 + tx*4 + 3]);
            }
            *(float4*)(C + m * Nn + n0 + tx*4) = v;
        }
    }

    if (epi == 2) {
        __syncthreads();
        if (tx < 2) {
#pragma unroll
            for (int i = 0; i < 4; i++) {
                xs[ty*4+i][tx*4+0] = lo32(acc[i][0]);
                xs[ty*4+i][tx*4+1] = hi32(acc[i][0]);
                xs[ty*4+i][tx*4+2] = lo32(acc[i][1]);
                xs[ty*4+i][tx*4+3] = hi32(acc[i][1]);
            }
        }
        __syncthreads();
        int d = tid;
        const float* dwp = dw + (ne*LL*DI + d)*RR;
        float wreg[RR];
#pragma unroll
        for (int r = 0; r < RR; r++) wreg[r] = dwp[r];
        float bv = db[ne*LL*DI + d];
#pragma unroll 4
        for (int row = 0; row < 64; row++) {
            float s = bv;
#pragma unroll
            for (int r = 0; r < RR; r++) s = fmaf(xs[row][r], wreg[r], s);
            s = (s > 20.f) ? s : log1pf(__expf(s));
            dtout[(ne*MM + m0 + row)*DI + d] = s;
        }
    }
#undef STAGE_STORE
#undef STAGE_COMPUTE
}

// ---------------- depthwise causal conv (K=4) + bias + SiLU ----------------
__global__ void k_conv(const float* __restrict__ cw, const float* __restrict__ cb, int l) {
    int idx = blockIdx.x * blockDim.x + threadIdx.x;  // NE*MM*DI
    if (idx >= NE*MM*DI) return;
    int d   = idx % DI;
    int row = (idx / DI) % MM;
    int ne  = idx / (DI*MM);
    int t = row & (TT - 1);
    int rowbase = row - t;
    const float* w = cw + ((ne*LL + l)*DI + d)*KC;
    float s = cb[(ne*LL + l)*DI + d];
#pragma unroll
    for (int k = 0; k < KC; k++) {
        int tt = t - (KC - 1) + k;
        if (tt >= 0)
            s = fmaf(g_xz[(ne*MM + rowbase + tt)*2*DI + d], w[k], s);
    }
    g_xc[idx] = siluf(s);
}

// ---------------- selective scan: one thread per (ne,b,d,n), 8x unrolled ----------------
__global__ void __launch_bounds__(256) k_scan(
    const float* __restrict__ alog, const float* __restrict__ dvec, int l)
{
    int gid = blockIdx.x * blockDim.x + threadIdx.x;  // NE*BB*DI*SN
    int n  = gid & 15;
    int d  = (gid >> 4) & (DI - 1);
    int b  = (gid >> 12) & (BB - 1);
    int ne = gid >> 15;
    float A  = -__expf(alog[((ne*LL + l)*DI + d)*SN + n]);
    float Dv = dvec[(ne*LL + l)*DI + d];
    int row = (ne*BB + b) * TT;
    const float* __restrict__ pdt = g_dt  + row*DI + d;
    const float* __restrict__ pxc = g_xc  + row*DI + d;
    const float* __restrict__ pxd = g_xdbl + row*40;
    const float* __restrict__ pz  = g_xz  + row*2*DI + DI + d;
    float* __restrict__ py = g_y + row*DI + d;
    float h = 0.f;

    for (int t0 = 0; t0 < TT; t0 += 8) {
        float dtv[8], xcv[8], Bv[8], Cv[8];
#pragma unroll
        for (int u = 0; u < 8; u++) {
            int t = t0 + u;
            dtv[u] = pdt[t*DI];
            xcv[u] = pxc[t*DI];
            Bv[u]  = pxd[t*40 + 8 + n];
            Cv[u]  = pxd[t*40 + 24 + n];
        }
        float dA[8];
#pragma unroll
        for (int u = 0; u < 8; u++) dA[u] = __expf(dtv[u] * A);
        float acc[8];
#pragma unroll
        for (int u = 0; u < 8; u++) {
            h = fmaf(dA[u], h, dtv[u] * Bv[u] * xcv[u]);
            acc[u] = h * Cv[u];
        }
#pragma unroll
        for (int u = 0; u < 8; u++) acc[u] += __shfl_xor_sync(0xffffffffu, acc[u], 8);
#pragma unroll
        for (int u = 0; u < 8; u++) acc[u] += __shfl_xor_sync(0xffffffffu, acc[u], 4);
#pragma unroll
        for (int u = 0; u < 8; u++) acc[u] += __shfl_xor_sync(0xffffffffu, acc[u], 2);
#pragma unroll
        for (int u = 0; u < 8; u++) acc[u] += __shfl_xor_sync(0xffffffffu, acc[u], 1);
        if (n == 0) {
#pragma unroll
            for (int u = 0; u < 8; u++) {
                int t = t0 + u;
                float z = pz[t*2*DI];
                py[t*DI] = (acc[u] + Dv*xcv[u]) * siluf(z);
            }
        }
    }
}

// ---------------- hyperbolic epilogue: one warp per row ----------------
__global__ void __launch_bounds__(256) k_hyper(float* __restrict__ out) {
    int tid  = threadIdx.x;
    int lane = tid & 31;
    int row  = blockIdx.x * 8 + (tid >> 5);
    const int offH  = 3*MM*EE;
    const int offCT = offH + 3*MM*(EE+1);
    const int offCH = offCT + MM*EE;
    float acc0 = 0.f, acc1 = 0.f;

#pragma unroll
    for (int ne = 0; ne < NE; ne++) {
        const float* p = out + ne*MM*EE + row*EE;
        float v0 = p[lane], v1 = p[lane+32];
        float sq = fmaf(v0, v0, v1*v1);
#pragma unroll
        for (int s = 16; s >= 1; s >>= 1) sq += __shfl_xor_sync(0xffffffffu, sq, s);
        float s2 = sq;
        float nn = sqrtf(s2);
        float ns = fmaxf(nn, EPSF);
        float sh = sinhf(ns);
        float scale = sh / ns;
        float s2x = scale*scale*s2;
        float x0 = sqrtf(1.f + s2x);
        float* ph = out + offH + ne*MM*(EE+1) + row*(EE+1);
        if (lane == 0) ph[0] = x0;
        ph[1+lane]    = scale * v0;
        ph[1+lane+32] = scale * v1;
        float nxs = sqrtf(s2x);
        float xm = fmaxf(x0, 1.f + EPSF);
        float dd = logf(xm + sqrtf(fmaxf(xm*xm - 1.f, 0.f)));
        float f = dd / fmaxf(nxs, EPSF) * scale;
        acc0 = fmaf(f, v0, acc0);
        acc1 = fmaf(f, v1, acc1);
    }
    float* pct = out + offCT + row*EE;
    pct[lane]    = acc0;
    pct[lane+32] = acc1;
    float sq = fmaf(acc0, acc0, acc1*acc1);
#pragma unroll
    for (int s = 16; s >= 1; s >>= 1) sq += __shfl_xor_sync(0xffffffffu, sq, s);
    float s2 = sq;
    float nn = sqrtf(s2);
    float ns = fmaxf(nn, EPSF);
    float sh = sinhf(ns);
    float scale = sh / ns;
    float s2x = scale*scale*s2;
    float x0 = sqrtf(1.f + s2x);
    float* pch = out + offCH + row*(EE+1);
    if (lane == 0) pch[0] = x0;
    pch[1+lane]    = scale * acc0;
    pch[1+lane+32] = scale * acc1;
}

// ---------------- launcher ----------------
extern "C" void kernel_launch(void* const* d_in, const int* in_sizes, int n_in,
                              void* d_out, int out_size) {
    const float* x       = (const float*)d_in[0];
    const float* einw    = (const float*)d_in[1];
    const float* einb    = (const float*)d_in[2];
    const float* minw    = (const float*)d_in[3];
    const float* mconvw  = (const float*)d_in[4];
    const float* mconvb  = (const float*)d_in[5];
    const float* mxprojw = (const float*)d_in[6];
    const float* mdtw    = (const float*)d_in[7];
    const float* mdtb    = (const float*)d_in[8];
    const float* malog   = (const float*)d_in[9];
    const float* md      = (const float*)d_in[10];
    const float* moutw   = (const float*)d_in[11];
    const float* eoutw   = (const float*)d_in[12];
    const float* eoutb   = (const float*)d_in[13];
    float* out = (float*)d_out;

    float *h0, *h1, *xz, *xc, *xdbl, *dtb, *yb;
    cudaGetSymbolAddress((void**)&h0,   g_h0);
    cudaGetSymbolAddress((void**)&h1,   g_h1);
    cudaGetSymbolAddress((void**)&xz,   g_xz);
    cudaGetSymbolAddress((void**)&xc,   g_xc);
    cudaGetSymbolAddress((void**)&xdbl, g_xdbl);
    cudaGetSymbolAddress((void**)&dtb,  g_dt);
    cudaGetSymbolAddress((void**)&yb,   g_y);

    k_embed<<<(NE*MM*HH + 255)/256, 256>>>(x, einw, einb);

    float* hcur = h0;
    float* hnxt = h1;
    for (int l = 0; l < LL; l++) {
        // in-proj: (NE x 8192 x 512) = h @ in_w^T
        dim3 g1(MM/64, (2*DI)/64, NE);
        sgemm64<<<g1, 256>>>(hcur, minw + l*2*DI*HH, nullptr, xz,
                             2*DI, HH, MM*HH, LL*2*DI*HH, MM*2*DI, 0, 0, 2*DI,
                             nullptr, nullptr, nullptr);
        // conv + silu
        k_conv<<<(NE*MM*DI)/256, 256>>>(mconvw, mconvb, l);
        // x_dbl = xc @ xproj_w^T (N=40 guarded) + fused dt projection
        dim3 gx(MM/64, 1, NE);
        sgemm64<<<gx, 256>>>(xc, mxprojw + l*40*DI, nullptr, xdbl,
                             40, DI, MM*DI, LL*40*DI, MM*40, 0, 2, 40,
                             mdtw + l*DI*RR, mdtb + l*DI, dtb);
        // selective scan (fused D-skip + silu(z) gate)
        k_scan<<<(NE*BB*DI*SN)/256, 256>>>(malog, md, l);
        // out-proj: (NE x 8192 x 128) = y @ out_w^T
        dim3 g2(MM/64, HH/64, NE);
        sgemm64<<<g2, 256>>>(yb, moutw + l*HH*DI, nullptr, hnxt,
                             HH, DI, MM*DI, LL*HH*DI, MM*HH, 0, 0, HH,
                             nullptr, nullptr, nullptr);
        float* tmp = hcur; hcur = hnxt; hnxt = tmp;
    }

    // encoder out-proj with fused bias + tanh -> tangents into d_out
    dim3 g3(MM/64, 1, NE);
    sgemm64<<<g3, 256>>>(hcur, eoutw, eoutb, out,
                         EE, HH, MM*HH, EE*HH, MM*EE, EE, 1, EE,
                         nullptr, nullptr, nullptr);

    // hyperbolic maps + combination (one warp per row)
    k_hyper<<<MM/8, 256>>>(out);
}

// round 8
// speedup vs baseline: 1.1539x; 1.1539x over previous
#include <cuda_runtime.h>
#include <cuda_bf16.h>
#include <math.h>

#define NE 3
#define BB 8
#define TT 1024
#define HH 128
#define EE 64
#define LL 3
#define DI 256
#define SN 16
#define KC 4
#define RR 8
#define MM (BB*TT)         // 8192 rows per encoder
#define EPSF 1e-7f

// ---------------- scratch (no allocations allowed) ----------------
__device__ float g_h0[NE*MM*HH];
__device__ float g_h1[NE*MM*HH];
__device__ float g_xz[NE*MM*2*DI];
__device__ float g_xc[NE*MM*DI];
__device__ float g_xdbl[NE*MM*40];
__device__ float g_dt[NE*MM*DI];
__device__ float g_y[NE*MM*DI];

__device__ __forceinline__ float siluf(float v) { return v / (1.f + __expf(-v)); }

// ---------------- embed: h = x * w + b ----------------
__global__ void k_embed(const float* __restrict__ x, const float* __restrict__ w,
                        const float* __restrict__ b) {
    int idx = blockIdx.x * blockDim.x + threadIdx.x;
    if (idx >= NE*MM*HH) return;
    int hh  = idx % HH;
    int row = (idx / HH) % MM;
    int ne  = idx / (HH*MM);
    g_h0[idx] = x[ne*MM + row] * w[ne*HH + hh] + b[ne*HH + hh];
}

// ======================= bf16 split tensor-core GEMM =======================
// C[m][n] = sum_k A[m][k] * W[n][k], fp32 in/out.
// Split each operand x = hi + lo (bf16 each); C = ah*bh + ah*bl + al*bh (fp32 acc).
// Block tile 128x128, BK=16, 8 warps (2m x 4n), warp tile 64x32.
__device__ __forceinline__ void mma16816(float* c, const unsigned* a, const unsigned* b) {
    asm volatile("mma.sync.aligned.m16n8k16.row.col.f32.bf16.bf16.f32 "
        "{%0,%1,%2,%3}, {%4,%5,%6,%7}, {%8,%9}, {%0,%1,%2,%3};"
        : "+f"(c[0]), "+f"(c[1]), "+f"(c[2]), "+f"(c[3])
        : "r"(a[0]), "r"(a[1]), "r"(a[2]), "r"(a[3]), "r"(b[0]), "r"(b[1]));
}

__device__ __forceinline__ void bsplit(float2 v, unsigned& hi, unsigned& lo) {
    __nv_bfloat162 h = __float22bfloat162_rn(v);
    float2 r = make_float2(v.x - __bfloat162float(h.x), v.y - __bfloat162float(h.y));
    __nv_bfloat162 l = __float22bfloat162_rn(r);
    hi = *(unsigned*)&h;
    lo = *(unsigned*)&l;
}

__global__ void __launch_bounds__(256) bgemm(
    const float* __restrict__ A, const float* __restrict__ W,
    float* __restrict__ C, int Nn, int Kk, int sA, int sW, int sC)
{
    __shared__ __align__(16) unsigned Ah[2][128][12];
    __shared__ __align__(16) unsigned Al[2][128][12];
    __shared__ __align__(16) unsigned Bh[2][128][12];
    __shared__ __align__(16) unsigned Bl[2][128][12];

    int ne = blockIdx.z;
    A += ne * sA; W += ne * sW; C += ne * sC;
    int m0 = blockIdx.x * 128, n0 = blockIdx.y * 128;
    int tid = threadIdx.x;
    int wid = tid >> 5, lane = tid & 31;
    int qr = lane >> 2, qc = lane & 3;
    int wm = wid >> 2, wn = wid & 3;     // 2 x 4 warp grid

    int ra = tid >> 1;                   // staging row (0..127)
    int kseg = (tid & 1) * 8;            // k offset 0 or 8
    int kp = (tid & 1) * 4;              // kpair offset 0 or 4
    const float* ap = A + (m0 + ra) * Kk + kseg;
    const float* wp = W + (n0 + ra) * Kk + kseg;

    float c[4][4][4];
#pragma unroll
    for (int i = 0; i < 4; i++)
#pragma unroll
        for (int j = 0; j < 4; j++)
#pragma unroll
            for (int q = 0; q < 4; q++) c[i][j][q] = 0.f;

    float4 va0, va1, vb0, vb1;

#define STAGE(buf)                                                            \
    {   unsigned h0,l0,h1,l1,h2,l2,h3,l3;                                     \
        bsplit(make_float2(va0.x, va0.y), h0, l0);                            \
        bsplit(make_float2(va0.z, va0.w), h1, l1);                            \
        bsplit(make_float2(va1.x, va1.y), h2, l2);                            \
        bsplit(make_float2(va1.z, va1.w), h3, l3);                            \
        *(uint4*)&Ah[buf][ra][kp] = make_uint4(h0, h1, h2, h3);               \
        *(uint4*)&Al[buf][ra][kp] = make_uint4(l0, l1, l2, l3);               \
        bsplit(make_float2(vb0.x, vb0.y), h0, l0);                            \
        bsplit(make_float2(vb0.z, vb0.w), h1, l1);                            \
        bsplit(make_float2(vb1.x, vb1.y), h2, l2);                            \
        bsplit(make_float2(vb1.z, vb1.w), h3, l3);                            \
        *(uint4*)&Bh[buf][ra][kp] = make_uint4(h0, h1, h2, h3);               \
        *(uint4*)&Bl[buf][ra][kp] = make_uint4(l0, l1, l2, l3);               \
    }

    // preload chunk 0
    va0 = *(const float4*)(ap);     va1 = *(const float4*)(ap + 4);
    vb0 = *(const float4*)(wp);     vb1 = *(const float4*)(wp + 4);
    STAGE(0);
    __syncthreads();

    int NC = Kk >> 4;
    int mb = 64 * wm, nb = 32 * wn;
    for (int kc = 0; kc < NC; kc++) {
        int buf = kc & 1;
        if (kc + 1 < NC) {
            int off = (kc + 1) * 16;
            va0 = *(const float4*)(ap + off);     va1 = *(const float4*)(ap + off + 4);
            vb0 = *(const float4*)(wp + off);     vb1 = *(const float4*)(wp + off + 4);
        }
        // B fragments (both split terms)
        unsigned bh[4][2], bl[4][2];
#pragma unroll
        for (int nf = 0; nf < 4; nf++) {
            int n = nb + 8 * nf + qr;
            bh[nf][0] = Bh[buf][n][qc]; bh[nf][1] = Bh[buf][n][qc + 4];
            bl[nf][0] = Bl[buf][n][qc]; bl[nf][1] = Bl[buf][n][qc + 4];
        }
#pragma unroll
        for (int mf = 0; mf < 4; mf++) {
            int m = mb + 16 * mf + qr;
            unsigned ah[4] = {Ah[buf][m][qc], Ah[buf][m + 8][qc],
                              Ah[buf][m][qc + 4], Ah[buf][m + 8][qc + 4]};
            unsigned al[4] = {Al[buf][m][qc], Al[buf][m + 8][qc],
                              Al[buf][m][qc + 4], Al[buf][m + 8][qc + 4]};
#pragma unroll
            for (int nf = 0; nf < 4; nf++) {
                mma16816(c[mf][nf], ah, bh[nf]);
                mma16816(c[mf][nf], ah, bl[nf]);
                mma16816(c[mf][nf], al, bh[nf]);
            }
        }
        if (kc + 1 < NC) STAGE(buf ^ 1);
        __syncthreads();
    }
#undef STAGE

    // epilogue
#pragma unroll
    for (int mf = 0; mf < 4; mf++) {
#pragma unroll
        for (int nf = 0; nf < 4; nf++) {
            int r  = m0 + mb + 16 * mf + qr;
            int cc = n0 + nb + 8 * nf + 2 * qc;
            *(float2*)(C + r * Nn + cc)       = make_float2(c[mf][nf][0], c[mf][nf][1]);
            *(float2*)(C + (r + 8) * Nn + cc) = make_float2(c[mf][nf][2], c[mf][nf][3]);
        }
    }
}

// ======== universal SGEMM: 64x64 tile, BK=16, 4x4 microtile, double-buffered ========
// (used for xdbl epi=2 and encoder-out epi=1)
__global__ void __launch_bounds__(256) sgemm64(
    const float* __restrict__ A, const float* __restrict__ W,
    const float* __restrict__ bias, float* __restrict__ C,
    int Nn, int Kk, int sA, int sW, int sC, int sBias, int epi, int Nvalid,
    const float* __restrict__ dw, const float* __restrict__ db,
    float* __restrict__ dtout)
{
    __shared__ float As[2][16][68];
    __shared__ float Bs[2][16][68];
    __shared__ float xs[64][9];

    int ne = blockIdx.z;
    A += ne * sA; W += ne * sW; C += ne * sC;
    int m0 = blockIdx.x * 64, n0 = blockIdx.y * 64;
    int tid = threadIdx.x;
    int tx = tid & 15, ty = tid >> 4;
    int lr = tid >> 2;
    int kq = (tid & 3) * 4;

    const float* ap = A + (m0 + lr) * Kk + kq;
    bool wok = (n0 + lr) < Nvalid;
    const float* wp = W + (wok ? (n0 + lr) : 0) * Kk + kq;

    float acc[4][4];
#pragma unroll
    for (int i = 0; i < 4; i++)
#pragma unroll
        for (int j = 0; j < 4; j++) acc[i][j] = 0.f;

    float4 av, wv;
    const float4 fz = make_float4(0.f, 0.f, 0.f, 0.f);

#define STAGE_STORE(buf)                                                     \
    { As[buf][kq+0][lr] = av.x; As[buf][kq+1][lr] = av.y;                    \
      As[buf][kq+2][lr] = av.z; As[buf][kq+3][lr] = av.w;                    \
      Bs[buf][kq+0][lr] = wv.x; Bs[buf][kq+1][lr] = wv.y;                    \
      Bs[buf][kq+2][lr] = wv.z; Bs[buf][kq+3][lr] = wv.w; }

#define STAGE_COMPUTE(buf)                                                   \
    _Pragma("unroll")                                                        \
    for (int k = 0; k < 16; k++) {                                           \
        float4 a = *(const float4*)&As[buf][k][ty*4];                        \
        float4 b = *(const float4*)&Bs[buf][k][tx*4];                        \
        float ar[4] = {a.x, a.y, a.z, a.w};                                  \
        float br[4] = {b.x, b.y, b.z, b.w};                                  \
        _Pragma("unroll")                                                    \
        for (int i = 0; i < 4; i++)                                          \
            _Pragma("unroll")                                                \
            for (int j = 0; j < 4; j++)                                      \
                acc[i][j] = fmaf(ar[i], br[j], acc[i][j]);                   \
    }

    av = *(const float4*)ap;
    wv = wok ? *(const float4*)wp : fz;
    STAGE_STORE(0);
    __syncthreads();

    for (int k0 = 0; k0 < Kk; k0 += 32) {
        bool l1 = (k0 + 16) < Kk;
        if (l1) {
            av = *(const float4*)(ap + k0 + 16);
            wv = wok ? *(const float4*)(wp + k0 + 16) : fz;
        }
        STAGE_COMPUTE(0);
        if (l1) { STAGE_STORE(1); __syncthreads(); }
        bool l2 = (k0 + 32) < Kk;
        if (l2) {
            av = *(const float4*)(ap + k0 + 32);
            wv = wok ? *(const float4*)(wp + k0 + 32) : fz;
        }
        if (l1) STAGE_COMPUTE(1);
        if (l2) { STAGE_STORE(0); __syncthreads(); }
    }

    if (n0 + tx*4 < Nvalid) {
#pragma unroll
        for (int i = 0; i < 4; i++) {
            int m = m0 + ty*4 + i;
            float4 v = make_float4(acc[i][0], acc[i][1], acc[i][2], acc[i][3]);
            if (epi == 1) {
                v.x = tanhf(v.x + bias[ne*sBias + n0 + tx*4 + 0]);
                v.y = tanhf(v.y + bias[ne*sBias + n0 + tx*4 + 1]);
                v.z = tanhf(v.z + bias[ne*sBias + n0 + tx*4 + 2]);
                v.w = tanhf(v.w + bias[ne*sBias + n0 + tx*4 + 3]);
            }
            *(float4*)(C + m * Nn + n0 + tx*4) = v;
        }
    }

    if (epi == 2) {
        __syncthreads();
        if (tx < 2) {
#pragma unroll
            for (int i = 0; i < 4; i++)
#pragma unroll
                for (int j = 0; j < 4; j++) xs[ty*4+i][tx*4+j] = acc[i][j];
        }
        __syncthreads();
        int d = tid;
        const float* dwp = dw + (ne*LL*DI + d)*RR;
        float wreg[RR];
#pragma unroll
        for (int r = 0; r < RR; r++) wreg[r] = dwp[r];
        float bv = db[ne*LL*DI + d];
#pragma unroll 4
        for (int row = 0; row < 64; row++) {
            float s = bv;
#pragma unroll
            for (int r = 0; r < RR; r++) s = fmaf(xs[row][r], wreg[r], s);
            s = (s > 20.f) ? s : log1pf(__expf(s));
            dtout[(ne*MM + m0 + row)*DI + d] = s;
        }
    }
#undef STAGE_STORE
#undef STAGE_COMPUTE
}

// ---------------- depthwise causal conv (K=4) + bias + SiLU ----------------
__global__ void k_conv(const float* __restrict__ cw, const float* __restrict__ cb, int l) {
    int idx = blockIdx.x * blockDim.x + threadIdx.x;  // NE*MM*DI
    if (idx >= NE*MM*DI) return;
    int d   = idx % DI;
    int row = (idx / DI) % MM;
    int ne  = idx / (DI*MM);
    int t = row & (TT - 1);
    int rowbase = row - t;
    const float* w = cw + ((ne*LL + l)*DI + d)*KC;
    float s = cb[(ne*LL + l)*DI + d];
#pragma unroll
    for (int k = 0; k < KC; k++) {
        int tt = t - (KC - 1) + k;
        if (tt >= 0)
            s = fmaf(g_xz[(ne*MM + rowbase + tt)*2*DI + d], w[k], s);
    }
    g_xc[idx] = siluf(s);
}

// ---------------- selective scan: one thread per (ne,b,d,n), 8x unrolled ----------------
__global__ void __launch_bounds__(256) k_scan(
    const float* __restrict__ alog, const float* __restrict__ dvec, int l)
{
    int gid = blockIdx.x * blockDim.x + threadIdx.x;  // NE*BB*DI*SN
    int n  = gid & 15;
    int d  = (gid >> 4) & (DI - 1);
    int b  = (gid >> 12) & (BB - 1);
    int ne = gid >> 15;
    float A  = -__expf(alog[((ne*LL + l)*DI + d)*SN + n]);
    float Dv = dvec[(ne*LL + l)*DI + d];
    int row = (ne*BB + b) * TT;
    const float* __restrict__ pdt = g_dt  + row*DI + d;
    const float* __restrict__ pxc = g_xc  + row*DI + d;
    const float* __restrict__ pxd = g_xdbl + row*40;
    const float* __restrict__ pz  = g_xz  + row*2*DI + DI + d;
    float* __restrict__ py = g_y + row*DI + d;
    float h = 0.f;

    for (int t0 = 0; t0 < TT; t0 += 8) {
        float dtv[8], xcv[8], Bv[8], Cv[8];
#pragma unroll
        for (int u = 0; u < 8; u++) {
            int t = t0 + u;
            dtv[u] = pdt[t*DI];
            xcv[u] = pxc[t*DI];
            Bv[u]  = pxd[t*40 + 8 + n];
            Cv[u]  = pxd[t*40 + 24 + n];
        }
        float dA[8];
#pragma unroll
        for (int u = 0; u < 8; u++) dA[u] = __expf(dtv[u] * A);
        float acc[8];
#pragma unroll
        for (int u = 0; u < 8; u++) {
            h = fmaf(dA[u], h, dtv[u] * Bv[u] * xcv[u]);
            acc[u] = h * Cv[u];
        }
#pragma unroll
        for (int u = 0; u < 8; u++) acc[u] += __shfl_xor_sync(0xffffffffu, acc[u], 8);
#pragma unroll
        for (int u = 0; u < 8; u++) acc[u] += __shfl_xor_sync(0xffffffffu, acc[u], 4);
#pragma unroll
        for (int u = 0; u < 8; u++) acc[u] += __shfl_xor_sync(0xffffffffu, acc[u], 2);
#pragma unroll
        for (int u = 0; u < 8; u++) acc[u] += __shfl_xor_sync(0xffffffffu, acc[u], 1);
        if (n == 0) {
#pragma unroll
            for (int u = 0; u < 8; u++) {
                int t = t0 + u;
                float z = pz[t*2*DI];
                py[t*DI] = (acc[u] + Dv*xcv[u]) * siluf(z);
            }
        }
    }
}

// ---------------- hyperbolic epilogue: one warp per row ----------------
__global__ void __launch_bounds__(256) k_hyper(float* __restrict__ out) {
    int tid  = threadIdx.x;
    int lane = tid & 31;
    int row  = blockIdx.x * 8 + (tid >> 5);
    const int offH  = 3*MM*EE;
    const int offCT = offH + 3*MM*(EE+1);
    const int offCH = offCT + MM*EE;
    float acc0 = 0.f, acc1 = 0.f;

#pragma unroll
    for (int ne = 0; ne < NE; ne++) {
        const float* p = out + ne*MM*EE + row*EE;
        float v0 = p[lane], v1 = p[lane+32];
        float sq = fmaf(v0, v0, v1*v1);
#pragma unroll
        for (int s = 16; s >= 1; s >>= 1) sq += __shfl_xor_sync(0xffffffffu, sq, s);
        float s2 = sq;
        float nn = sqrtf(s2);
        float ns = fmaxf(nn, EPSF);
        float sh = sinhf(ns);
        float scale = sh / ns;
        float s2x = scale*scale*s2;
        float x0 = sqrtf(1.f + s2x);
        float* ph = out + offH + ne*MM*(EE+1) + row*(EE+1);
        if (lane == 0) ph[0] = x0;
        ph[1+lane]    = scale * v0;
        ph[1+lane+32] = scale * v1;
        float nxs = sqrtf(s2x);
        float xm = fmaxf(x0, 1.f + EPSF);
        float dd = logf(xm + sqrtf(fmaxf(xm*xm - 1.f, 0.f)));
        float f = dd / fmaxf(nxs, EPSF) * scale;
        acc0 = fmaf(f, v0, acc0);
        acc1 = fmaf(f, v1, acc1);
    }
    float* pct = out + offCT + row*EE;
    pct[lane]    = acc0;
    pct[lane+32] = acc1;
    float sq = fmaf(acc0, acc0, acc1*acc1);
#pragma unroll
    for (int s = 16; s >= 1; s >>= 1) sq += __shfl_xor_sync(0xffffffffu, sq, s);
    float s2 = sq;
    float nn = sqrtf(s2);
    float ns = fmaxf(nn, EPSF);
    float sh = sinhf(ns);
    float scale = sh / ns;
    float s2x = scale*scale*s2;
    float x0 = sqrtf(1.f + s2x);
    float* pch = out + offCH + row*(EE+1);
    if (lane == 0) pch[0] = x0;
    pch[1+lane]    = scale * acc0;
    pch[1+lane+32] = scale * acc1;
}

// ---------------- launcher ----------------
extern "C" void kernel_launch(void* const* d_in, const int* in_sizes, int n_in,
                              void* d_out, int out_size) {
    const float* x       = (const float*)d_in[0];
    const float* einw    = (const float*)d_in[1];
    const float* einb    = (const float*)d_in[2];
    const float* minw    = (const float*)d_in[3];
    const float* mconvw  = (const float*)d_in[4];
    const float* mconvb  = (const float*)d_in[5];
    const float* mxprojw = (const float*)d_in[6];
    const float* mdtw    = (const float*)d_in[7];
    const float* mdtb    = (const float*)d_in[8];
    const float* malog   = (const float*)d_in[9];
    const float* md      = (const float*)d_in[10];
    const float* moutw   = (const float*)d_in[11];
    const float* eoutw   = (const float*)d_in[12];
    const float* eoutb   = (const float*)d_in[13];
    float* out = (float*)d_out;

    float *h0, *h1, *xz, *xc, *xdbl, *dtb, *yb;
    cudaGetSymbolAddress((void**)&h0,   g_h0);
    cudaGetSymbolAddress((void**)&h1,   g_h1);
    cudaGetSymbolAddress((void**)&xz,   g_xz);
    cudaGetSymbolAddress((void**)&xc,   g_xc);
    cudaGetSymbolAddress((void**)&xdbl, g_xdbl);
    cudaGetSymbolAddress((void**)&dtb,  g_dt);
    cudaGetSymbolAddress((void**)&yb,   g_y);

    k_embed<<<(NE*MM*HH + 255)/256, 256>>>(x, einw, einb);

    float* hcur = h0;
    float* hnxt = h1;
    for (int l = 0; l < LL; l++) {
        // in-proj: (NE x 8192 x 512) = h @ in_w^T  -- tensor cores
        dim3 g1(MM/128, (2*DI)/128, NE);
        bgemm<<<g1, 256>>>(hcur, minw + l*2*DI*HH, xz,
                           2*DI, HH, MM*HH, LL*2*DI*HH, MM*2*DI);
        // conv + silu
        k_conv<<<(NE*MM*DI)/256, 256>>>(mconvw, mconvb, l);
        // x_dbl = xc @ xproj_w^T (N=40 guarded) + fused dt projection
        dim3 gx(MM/64, 1, NE);
        sgemm64<<<gx, 256>>>(xc, mxprojw + l*40*DI, nullptr, xdbl,
                             40, DI, MM*DI, LL*40*DI, MM*40, 0, 2, 40,
                             mdtw + l*DI*RR, mdtb + l*DI, dtb);
        // selective scan (fused D-skip + silu(z) gate)
        k_scan<<<(NE*BB*DI*SN)/256, 256>>>(malog, md, l);
        // out-proj: (NE x 8192 x 128) = y @ out_w^T  -- tensor cores
        dim3 g2(MM/128, HH/128, NE);
        bgemm<<<g2, 256>>>(yb, moutw + l*HH*DI, hnxt,
                           HH, DI, MM*DI, LL*HH*DI, MM*HH);
        float* tmp = hcur; hcur = hnxt; hnxt = tmp;
    }

    // encoder out-proj with fused bias + tanh -> tangents into d_out
    dim3 g3(MM/64, 1, NE);
    sgemm64<<<g3, 256>>>(hcur, eoutw, eoutb, out,
                         EE, HH, MM*HH, EE*HH, MM*EE, EE, 1, EE,
                         nullptr, nullptr, nullptr);

    // hyperbolic maps + combination (one warp per row)
    k_hyper<<<MM/8, 256>>>(out);
}